// round 12
// baseline (speedup 1.0000x reference)
#include <cuda_runtime.h>
#include <cstdint>

// ---------------------------------------------------------------------------
// GCN 2-layer + linear head. Bucketed CSR, pre-scaled features, packed-f32x2
// gathers (16 lanes/node), scalar fused GEMM (R9 form):
//   xs   = dinv .* x
//   aggx = dinv[d] .* (sum xs[src] + xs[d])
//   t2s  = dinv .* ( relu(aggx@W1 + b1) @ W2 )
//   out  = relu( dinv[d].*(sum t2s[src] + t2s[d]) + b2 ) @ Wl + bl
// ---------------------------------------------------------------------------

#define N_NODES 50000
#define CAP 64

#define ADD_F32X2(out, a, b) \
    asm("add.rn.f32x2 %0, %1, %2;" : "=l"(out) : "l"(a), "l"(b))

__device__ __forceinline__ float2 unpack2(unsigned long long v) {
    unsigned lo, hi;
    asm("mov.b64 {%0, %1}, %2;" : "=r"(lo), "=r"(hi) : "l"(v));
    float2 r;
    r.x = __uint_as_float(lo);
    r.y = __uint_as_float(hi);
    return r;
}

__device__ int   g_cnt[N_NODES];
__device__ int   g_bkt[(size_t)N_NODES * CAP];
__device__ float g_dinv[N_NODES];
__device__ float g_xs[(size_t)N_NODES * 32];
__device__ float g_aggx[(size_t)N_NODES * 32];
__device__ float g_t2[(size_t)N_NODES * 64];
__device__ int   g_is64;

// ---------------- init: zero counts + dtype detect (block 0) ----------------
__global__ void k_init(const unsigned int* __restrict__ w, int nwords, int n) {
    int i = blockIdx.x * blockDim.x + threadIdx.x;
    if (i < n) g_cnt[i] = 0;
    if (blockIdx.x == 0) {
        __shared__ int any_nz;
        if (threadIdx.x == 0) any_nz = 0;
        __syncthreads();
        for (int j = threadIdx.x * 2 + 1; j < nwords; j += blockDim.x * 2) {
            if (w[j] != 0u) { any_nz = 1; break; }
        }
        __syncthreads();
        if (threadIdx.x == 0) g_is64 = any_nz ? 0 : 1;
    }
}

// ---------------- bucket fill: 1 edge/thread ----------------
__global__ void k_fill(const void* __restrict__ ei, int E) {
    int e = blockIdx.x * blockDim.x + threadIdx.x;
    if (e >= E) return;
    int s, d;
    if (g_is64) {
        const long long* q = (const long long*)ei;
        s = (int)q[e]; d = (int)q[E + e];
    } else {
        const int* q = (const int*)ei;
        s = q[e]; d = q[E + e];
    }
    int slot = atomicAdd(&g_cnt[d], 1);
    if (slot < CAP) g_bkt[(size_t)d * CAP + slot] = s;
}

// ---------------- dinv + xs = dinv .* x  (warp per node) ----------------
__global__ void k_dinv_xs(const float* __restrict__ x, int n) {
    int warp = (blockIdx.x * blockDim.x + threadIdx.x) >> 5;
    if (warp >= n) return;
    int lane = threadIdx.x & 31;
    float dv = rsqrtf((float)(g_cnt[warp] + 1));
    if (lane == 0) g_dinv[warp] = dv;
    g_xs[(size_t)warp * 32 + lane] = x[(size_t)warp * 32 + lane] * dv;
}

// ------- gather x: 16 lanes/node, float2/lane, unroll 8 for MLP -------
__global__ void k_gather_x(int n) {
    int node = (blockIdx.x * blockDim.x + threadIdx.x) >> 4;
    if (node >= n) return;
    int lane = threadIdx.x & 15;

    int cnt = g_cnt[node];
    if (cnt > CAP) cnt = CAP;
    const float dv = g_dinv[node];
    const int* bkt = g_bkt + (size_t)node * CAP;
    const unsigned long long* xs2 = reinterpret_cast<const unsigned long long*>(g_xs);

    unsigned long long a = xs2[(size_t)node * 16 + lane];  // self (pre-scaled)
    unsigned long long b = 0ull, c = 0ull, d = 0ull;

    int e = 0;
    // 8 independent loads in flight per iteration
    for (; e + 8 <= cnt; e += 8) {
        int4 sA = *reinterpret_cast<const int4*>(bkt + e);
        int4 sB = *reinterpret_cast<const int4*>(bkt + e + 4);
        unsigned long long v0 = xs2[(size_t)sA.x * 16 + lane];
        unsigned long long v1 = xs2[(size_t)sA.y * 16 + lane];
        unsigned long long v2 = xs2[(size_t)sA.z * 16 + lane];
        unsigned long long v3 = xs2[(size_t)sA.w * 16 + lane];
        unsigned long long v4 = xs2[(size_t)sB.x * 16 + lane];
        unsigned long long v5 = xs2[(size_t)sB.y * 16 + lane];
        unsigned long long v6 = xs2[(size_t)sB.z * 16 + lane];
        unsigned long long v7 = xs2[(size_t)sB.w * 16 + lane];
        ADD_F32X2(a, a, v0);
        ADD_F32X2(b, b, v1);
        ADD_F32X2(c, c, v2);
        ADD_F32X2(d, d, v3);
        ADD_F32X2(a, a, v4);
        ADD_F32X2(b, b, v5);
        ADD_F32X2(c, c, v6);
        ADD_F32X2(d, d, v7);
    }
    if (e + 4 <= cnt) {
        int4 s4 = *reinterpret_cast<const int4*>(bkt + e);
        unsigned long long v0 = xs2[(size_t)s4.x * 16 + lane];
        unsigned long long v1 = xs2[(size_t)s4.y * 16 + lane];
        unsigned long long v2 = xs2[(size_t)s4.z * 16 + lane];
        unsigned long long v3 = xs2[(size_t)s4.w * 16 + lane];
        ADD_F32X2(a, a, v0);
        ADD_F32X2(b, b, v1);
        ADD_F32X2(c, c, v2);
        ADD_F32X2(d, d, v3);
        e += 4;
    }
    for (; e < cnt; e++) {
        unsigned long long v0 = xs2[(size_t)bkt[e] * 16 + lane];
        ADD_F32X2(a, a, v0);
    }

    ADD_F32X2(a, a, b);
    ADD_F32X2(c, c, d);
    ADD_F32X2(a, a, c);
    float2 r = unpack2(a);
    r.x *= dv; r.y *= dv;
    reinterpret_cast<float2*>(g_aggx)[(size_t)node * 16 + lane] = r;
}

// ---- fused GEMM (scalar, R9 form): t2s = dinv .* ( relu(aggx@W1+b1) @ W2 ) ----
__global__ void k_gemm_fused(const float* __restrict__ W1, const float* __restrict__ b1,
                             const float* __restrict__ W2, int n) {
    __shared__ float W1s[32 * 64];
    __shared__ float W2s[64 * 64];
    __shared__ float bs[64];
    for (int i = threadIdx.x; i < 32 * 64; i += blockDim.x) W1s[i] = W1[i];
    for (int i = threadIdx.x; i < 64 * 64; i += blockDim.x) W2s[i] = W2[i];
    for (int i = threadIdx.x; i < 64; i += blockDim.x) bs[i] = b1[i];
    __syncthreads();

    int node = blockIdx.x * blockDim.x + threadIdx.x;
    if (node >= n) return;

    float h1[64];
#pragma unroll
    for (int j = 0; j < 64; j++) h1[j] = bs[j];
    const float4* row4 = reinterpret_cast<const float4*>(g_aggx + (size_t)node * 32);
#pragma unroll
    for (int k4 = 0; k4 < 8; k4++) {
        float4 v4 = row4[k4];
        float v[4] = {v4.x, v4.y, v4.z, v4.w};
#pragma unroll
        for (int kk = 0; kk < 4; kk++) {
            int k = k4 * 4 + kk;
#pragma unroll
            for (int j = 0; j < 64; j++) h1[j] = fmaf(v[kk], W1s[k * 64 + j], h1[j]);
        }
    }
#pragma unroll
    for (int j = 0; j < 64; j++) h1[j] = fmaxf(h1[j], 0.f);

    const float dv = g_dinv[node];
    float4* o = reinterpret_cast<float4*>(g_t2 + (size_t)node * 64);
#pragma unroll
    for (int c = 0; c < 4; c++) {
        float acc[16];
#pragma unroll
        for (int j = 0; j < 16; j++) acc[j] = 0.f;
#pragma unroll
        for (int k = 0; k < 64; k++) {
            float v = h1[k];
#pragma unroll
            for (int j = 0; j < 16; j++)
                acc[j] = fmaf(v, W2s[k * 64 + c * 16 + j], acc[j]);
        }
#pragma unroll
        for (int j4 = 0; j4 < 4; j4++)
            o[c * 4 + j4] = make_float4(acc[4 * j4] * dv, acc[4 * j4 + 1] * dv,
                                        acc[4 * j4 + 2] * dv, acc[4 * j4 + 3] * dv);
    }
}

// ------ gather t2s + head: 16 lanes/node, float4/lane (2x f32x2) ------
__global__ void k_gather_head(const float* __restrict__ b2, const float* __restrict__ Wl,
                              const float* __restrict__ bl, float* __restrict__ out, int n) {
    __shared__ float bs[64];
    __shared__ float Ws[128];
    __shared__ float bls[2];
    for (int i = threadIdx.x; i < 64; i += blockDim.x) bs[i] = b2[i];
    for (int i = threadIdx.x; i < 128; i += blockDim.x) Ws[i] = Wl[i];
    if (threadIdx.x < 2) bls[threadIdx.x] = bl[threadIdx.x];
    __syncthreads();

    int node = (blockIdx.x * blockDim.x + threadIdx.x) >> 4;
    if (node >= n) return;
    int lane = threadIdx.x & 15;  // covers features 4*lane .. 4*lane+3

    int cnt = g_cnt[node];
    if (cnt > CAP) cnt = CAP;
    const float dv = g_dinv[node];
    const int* bkt = g_bkt + (size_t)node * CAP;
    const ulonglong2* hp = reinterpret_cast<const ulonglong2*>(g_t2);

    ulonglong2 self = hp[(size_t)node * 16 + lane];
    unsigned long long a0 = self.x, a1 = self.y;
    unsigned long long b0 = 0ull, b1v = 0ull;
    unsigned long long c0 = 0ull, c1 = 0ull;
    unsigned long long d0 = 0ull, d1 = 0ull;

    int e = 0;
    for (; e + 4 <= cnt; e += 4) {
        int4 s4 = *reinterpret_cast<const int4*>(bkt + e);
        ulonglong2 v0 = hp[(size_t)s4.x * 16 + lane];
        ulonglong2 v1 = hp[(size_t)s4.y * 16 + lane];
        ulonglong2 v2 = hp[(size_t)s4.z * 16 + lane];
        ulonglong2 v3 = hp[(size_t)s4.w * 16 + lane];
        ADD_F32X2(a0, a0, v0.x); ADD_F32X2(a1, a1, v0.y);
        ADD_F32X2(b0, b0, v1.x); ADD_F32X2(b1v, b1v, v1.y);
        ADD_F32X2(c0, c0, v2.x); ADD_F32X2(c1, c1, v2.y);
        ADD_F32X2(d0, d0, v3.x); ADD_F32X2(d1, d1, v3.y);
    }
    if (e + 2 <= cnt) {
        int s0 = bkt[e], s1 = bkt[e + 1];
        ulonglong2 v0 = hp[(size_t)s0 * 16 + lane];
        ulonglong2 v1 = hp[(size_t)s1 * 16 + lane];
        ADD_F32X2(a0, a0, v0.x); ADD_F32X2(a1, a1, v0.y);
        ADD_F32X2(b0, b0, v1.x); ADD_F32X2(b1v, b1v, v1.y);
        e += 2;
    }
    if (e < cnt) {
        ulonglong2 v0 = hp[(size_t)bkt[e] * 16 + lane];
        ADD_F32X2(a0, a0, v0.x); ADD_F32X2(a1, a1, v0.y);
    }

    ADD_F32X2(a0, a0, b0); ADD_F32X2(c0, c0, d0); ADD_F32X2(a0, a0, c0);
    ADD_F32X2(a1, a1, b1v); ADD_F32X2(c1, c1, d1); ADD_F32X2(a1, a1, c1);
    float2 p0 = unpack2(a0);
    float2 p1 = unpack2(a1);

    int k0 = 4 * lane;
    float f0 = fmaxf(p0.x * dv + bs[k0 + 0], 0.f);
    float f1 = fmaxf(p0.y * dv + bs[k0 + 1], 0.f);
    float f2 = fmaxf(p1.x * dv + bs[k0 + 2], 0.f);
    float f3 = fmaxf(p1.y * dv + bs[k0 + 3], 0.f);

    float q0 = f0 * Ws[(k0 + 0) * 2 + 0] + f1 * Ws[(k0 + 1) * 2 + 0]
             + f2 * Ws[(k0 + 2) * 2 + 0] + f3 * Ws[(k0 + 3) * 2 + 0];
    float q1 = f0 * Ws[(k0 + 0) * 2 + 1] + f1 * Ws[(k0 + 1) * 2 + 1]
             + f2 * Ws[(k0 + 2) * 2 + 1] + f3 * Ws[(k0 + 3) * 2 + 1];
#pragma unroll
    for (int off = 8; off > 0; off >>= 1) {
        q0 += __shfl_xor_sync(0xffffffffu, q0, off);
        q1 += __shfl_xor_sync(0xffffffffu, q1, off);
    }
    if (lane == 0) {
        out[(size_t)node * 2 + 0] = q0 + bls[0];
        out[(size_t)node * 2 + 1] = q1 + bls[1];
    }
}

// ---------------------------------------------------------------------------
extern "C" void kernel_launch(void* const* d_in, const int* in_sizes, int n_in,
                              void* d_out, int out_size) {
    const float* x   = (const float*)d_in[0];
    const void*  ei  = d_in[1];
    const float* W1  = (const float*)d_in[2];
    const float* b1  = (const float*)d_in[3];
    const float* W2  = (const float*)d_in[4];
    const float* b2  = (const float*)d_in[5];
    const float* Wl  = (const float*)d_in[6];
    const float* bl  = (const float*)d_in[7];
    float* out       = (float*)d_out;

    const int N = in_sizes[0] / 32;
    const int E = in_sizes[1] / 2;
    const int T = 256;

    int nwords = 2 * E < 4096 ? 2 * E : 4096;

    k_init<<<(N + T - 1) / T, T>>>((const unsigned int*)ei, nwords, N);
    k_fill<<<(E + T - 1) / T, T>>>(ei, E);

    const int GW32 = (N * 32 + T - 1) / T;  // warp-per-node
    const int GW16 = (N * 16 + T - 1) / T;  // 16 lanes/node

    k_dinv_xs<<<GW32, T>>>(x, N);
    k_gather_x<<<GW16, T>>>(N);
    k_gemm_fused<<<(N + 127) / 128, 128>>>(W1, b1, W2, N);
    k_gather_head<<<GW16, T>>>(b2, Wl, bl, out, N);
}

// round 13
// speedup vs baseline: 1.0232x; 1.0232x over previous
#include <cuda_runtime.h>
#include <cstdint>

// ---------------------------------------------------------------------------
// GCN 2-layer + linear head. Bucketed CSR, pre-scaled features, packed-f32x2
// gathers (16 lanes/node, R9 geometry). 5 kernels total:
//   fill (with in-block dtype detect; g_cnt pre-zeroed by module load /
//         previous launch's gather_head epilogue)
//   dinv_xs, gather_x, gemm_fused, gather_head (+ zeroes g_cnt for next call)
// ---------------------------------------------------------------------------

#define N_NODES 50000
#define CAP 64

#define ADD_F32X2(out, a, b) \
    asm("add.rn.f32x2 %0, %1, %2;" : "=l"(out) : "l"(a), "l"(b))

__device__ __forceinline__ float2 unpack2(unsigned long long v) {
    unsigned lo, hi;
    asm("mov.b64 {%0, %1}, %2;" : "=r"(lo), "=r"(hi) : "l"(v));
    float2 r;
    r.x = __uint_as_float(lo);
    r.y = __uint_as_float(hi);
    return r;
}

// zero-initialized at module load; re-zeroed by gather_head each launch
__device__ int   g_cnt[N_NODES];
__device__ int   g_bkt[(size_t)N_NODES * CAP];
__device__ float g_dinv[N_NODES];
__device__ float g_xs[(size_t)N_NODES * 32];
__device__ float g_aggx[(size_t)N_NODES * 32];
__device__ float g_t2[(size_t)N_NODES * 64];

// ---------------- bucket fill with per-block dtype detect ----------------
// int64 edge values < 50000 => odd 32-bit words of the index buffer are all 0.
// int32 edge data => first 256 odd words are random indices, ~never all zero.
__global__ void k_fill(const void* __restrict__ ei, int E, int nodd) {
    __shared__ int s_nz;
    if (threadIdx.x == 0) s_nz = 0;
    __syncthreads();
    {
        int j = 2 * (int)threadIdx.x + 1;
        if (j < nodd && ((const unsigned int*)ei)[j] != 0u) s_nz = 1;
    }
    __syncthreads();
    const bool is64 = (s_nz == 0);

    int e = blockIdx.x * blockDim.x + threadIdx.x;
    if (e >= E) return;
    int s, d;
    if (is64) {
        const long long* q = (const long long*)ei;
        s = (int)q[e]; d = (int)q[E + e];
    } else {
        const int* q = (const int*)ei;
        s = q[e]; d = q[E + e];
    }
    int slot = atomicAdd(&g_cnt[d], 1);
    if (slot < CAP) g_bkt[(size_t)d * CAP + slot] = s;
}

// ---------------- dinv + xs = dinv .* x  (warp per node) ----------------
__global__ void k_dinv_xs(const float* __restrict__ x, int n) {
    int warp = (blockIdx.x * blockDim.x + threadIdx.x) >> 5;
    if (warp >= n) return;
    int lane = threadIdx.x & 31;
    float dv = rsqrtf((float)(g_cnt[warp] + 1));
    if (lane == 0) g_dinv[warp] = dv;
    g_xs[(size_t)warp * 32 + lane] = x[(size_t)warp * 32 + lane] * dv;
}

// ------- gather x: 16 lanes/node, float2/lane, unroll 4 (R9 form) -------
__global__ void k_gather_x(int n) {
    int node = (blockIdx.x * blockDim.x + threadIdx.x) >> 4;
    if (node >= n) return;
    int lane = threadIdx.x & 15;

    int cnt = g_cnt[node];
    if (cnt > CAP) cnt = CAP;
    const float dv = g_dinv[node];
    const int* bkt = g_bkt + (size_t)node * CAP;
    const unsigned long long* xs2 = reinterpret_cast<const unsigned long long*>(g_xs);

    unsigned long long a = xs2[(size_t)node * 16 + lane];  // self (pre-scaled)
    unsigned long long b = 0ull, c = 0ull, d = 0ull;

    int e = 0;
    for (; e + 4 <= cnt; e += 4) {
        int4 s4 = *reinterpret_cast<const int4*>(bkt + e);
        unsigned long long v0 = xs2[(size_t)s4.x * 16 + lane];
        unsigned long long v1 = xs2[(size_t)s4.y * 16 + lane];
        unsigned long long v2 = xs2[(size_t)s4.z * 16 + lane];
        unsigned long long v3 = xs2[(size_t)s4.w * 16 + lane];
        ADD_F32X2(a, a, v0);
        ADD_F32X2(b, b, v1);
        ADD_F32X2(c, c, v2);
        ADD_F32X2(d, d, v3);
    }
    for (; e < cnt; e++) {
        unsigned long long v0 = xs2[(size_t)bkt[e] * 16 + lane];
        ADD_F32X2(a, a, v0);
    }

    ADD_F32X2(a, a, b);
    ADD_F32X2(c, c, d);
    ADD_F32X2(a, a, c);
    float2 r = unpack2(a);
    r.x *= dv; r.y *= dv;
    reinterpret_cast<float2*>(g_aggx)[(size_t)node * 16 + lane] = r;
}

// ---- fused GEMM (scalar, R9 form): t2s = dinv .* ( relu(aggx@W1+b1) @ W2 ) ----
__global__ void k_gemm_fused(const float* __restrict__ W1, const float* __restrict__ b1,
                             const float* __restrict__ W2, int n) {
    __shared__ float W1s[32 * 64];
    __shared__ float W2s[64 * 64];
    __shared__ float bs[64];
    for (int i = threadIdx.x; i < 32 * 64; i += blockDim.x) W1s[i] = W1[i];
    for (int i = threadIdx.x; i < 64 * 64; i += blockDim.x) W2s[i] = W2[i];
    for (int i = threadIdx.x; i < 64; i += blockDim.x) bs[i] = b1[i];
    __syncthreads();

    int node = blockIdx.x * blockDim.x + threadIdx.x;
    if (node >= n) return;

    float h1[64];
#pragma unroll
    for (int j = 0; j < 64; j++) h1[j] = bs[j];
    const float4* row4 = reinterpret_cast<const float4*>(g_aggx + (size_t)node * 32);
#pragma unroll
    for (int k4 = 0; k4 < 8; k4++) {
        float4 v4 = row4[k4];
        float v[4] = {v4.x, v4.y, v4.z, v4.w};
#pragma unroll
        for (int kk = 0; kk < 4; kk++) {
            int k = k4 * 4 + kk;
#pragma unroll
            for (int j = 0; j < 64; j++) h1[j] = fmaf(v[kk], W1s[k * 64 + j], h1[j]);
        }
    }
#pragma unroll
    for (int j = 0; j < 64; j++) h1[j] = fmaxf(h1[j], 0.f);

    const float dv = g_dinv[node];
    float4* o = reinterpret_cast<float4*>(g_t2 + (size_t)node * 64);
#pragma unroll
    for (int c = 0; c < 4; c++) {
        float acc[16];
#pragma unroll
        for (int j = 0; j < 16; j++) acc[j] = 0.f;
#pragma unroll
        for (int k = 0; k < 64; k++) {
            float v = h1[k];
#pragma unroll
            for (int j = 0; j < 16; j++)
                acc[j] = fmaf(v, W2s[k * 64 + c * 16 + j], acc[j]);
        }
#pragma unroll
        for (int j4 = 0; j4 < 4; j4++)
            o[c * 4 + j4] = make_float4(acc[4 * j4] * dv, acc[4 * j4 + 1] * dv,
                                        acc[4 * j4 + 2] * dv, acc[4 * j4 + 3] * dv);
    }
}

// ------ gather t2s + head; epilogue zeroes g_cnt for the next launch ------
__global__ void k_gather_head(const float* __restrict__ b2, const float* __restrict__ Wl,
                              const float* __restrict__ bl, float* __restrict__ out, int n) {
    __shared__ float bs[64];
    __shared__ float Ws[128];
    __shared__ float bls[2];
    for (int i = threadIdx.x; i < 64; i += blockDim.x) bs[i] = b2[i];
    for (int i = threadIdx.x; i < 128; i += blockDim.x) Ws[i] = Wl[i];
    if (threadIdx.x < 2) bls[threadIdx.x] = bl[threadIdx.x];
    __syncthreads();

    int node = (blockIdx.x * blockDim.x + threadIdx.x) >> 4;
    if (node >= n) return;
    int lane = threadIdx.x & 15;  // covers features 4*lane .. 4*lane+3

    int cnt = g_cnt[node];
    if (cnt > CAP) cnt = CAP;
    const float dv = g_dinv[node];
    const int* bkt = g_bkt + (size_t)node * CAP;
    const ulonglong2* hp = reinterpret_cast<const ulonglong2*>(g_t2);

    ulonglong2 self = hp[(size_t)node * 16 + lane];
    unsigned long long a0 = self.x, a1 = self.y;
    unsigned long long b0 = 0ull, b1v = 0ull;
    unsigned long long c0 = 0ull, c1 = 0ull;
    unsigned long long d0 = 0ull, d1 = 0ull;

    int e = 0;
    for (; e + 4 <= cnt; e += 4) {
        int4 s4 = *reinterpret_cast<const int4*>(bkt + e);
        ulonglong2 v0 = hp[(size_t)s4.x * 16 + lane];
        ulonglong2 v1 = hp[(size_t)s4.y * 16 + lane];
        ulonglong2 v2 = hp[(size_t)s4.z * 16 + lane];
        ulonglong2 v3 = hp[(size_t)s4.w * 16 + lane];
        ADD_F32X2(a0, a0, v0.x); ADD_F32X2(a1, a1, v0.y);
        ADD_F32X2(b0, b0, v1.x); ADD_F32X2(b1v, b1v, v1.y);
        ADD_F32X2(c0, c0, v2.x); ADD_F32X2(c1, c1, v2.y);
        ADD_F32X2(d0, d0, v3.x); ADD_F32X2(d1, d1, v3.y);
    }
    if (e + 2 <= cnt) {
        int s0 = bkt[e], s1 = bkt[e + 1];
        ulonglong2 v0 = hp[(size_t)s0 * 16 + lane];
        ulonglong2 v1 = hp[(size_t)s1 * 16 + lane];
        ADD_F32X2(a0, a0, v0.x); ADD_F32X2(a1, a1, v0.y);
        ADD_F32X2(b0, b0, v1.x); ADD_F32X2(b1v, b1v, v1.y);
        e += 2;
    }
    if (e < cnt) {
        ulonglong2 v0 = hp[(size_t)bkt[e] * 16 + lane];
        ADD_F32X2(a0, a0, v0.x); ADD_F32X2(a1, a1, v0.y);
    }

    ADD_F32X2(a0, a0, b0); ADD_F32X2(c0, c0, d0); ADD_F32X2(a0, a0, c0);
    ADD_F32X2(a1, a1, b1v); ADD_F32X2(c1, c1, d1); ADD_F32X2(a1, a1, c1);
    float2 p0 = unpack2(a0);
    float2 p1 = unpack2(a1);

    int k0 = 4 * lane;
    float f0 = fmaxf(p0.x * dv + bs[k0 + 0], 0.f);
    float f1 = fmaxf(p0.y * dv + bs[k0 + 1], 0.f);
    float f2 = fmaxf(p1.x * dv + bs[k0 + 2], 0.f);
    float f3 = fmaxf(p1.y * dv + bs[k0 + 3], 0.f);

    float q0 = f0 * Ws[(k0 + 0) * 2 + 0] + f1 * Ws[(k0 + 1) * 2 + 0]
             + f2 * Ws[(k0 + 2) * 2 + 0] + f3 * Ws[(k0 + 3) * 2 + 0];
    float q1 = f0 * Ws[(k0 + 0) * 2 + 1] + f1 * Ws[(k0 + 1) * 2 + 1]
             + f2 * Ws[(k0 + 2) * 2 + 1] + f3 * Ws[(k0 + 3) * 2 + 1];
#pragma unroll
    for (int off = 8; off > 0; off >>= 1) {
        q0 += __shfl_xor_sync(0xffffffffu, q0, off);
        q1 += __shfl_xor_sync(0xffffffffu, q1, off);
    }
    if (lane == 0) {
        out[(size_t)node * 2 + 0] = q0 + bls[0];
        out[(size_t)node * 2 + 1] = q1 + bls[1];
        g_cnt[node] = 0;  // hand the next launch a zeroed counter array
    }
}

// ---------------------------------------------------------------------------
extern "C" void kernel_launch(void* const* d_in, const int* in_sizes, int n_in,
                              void* d_out, int out_size) {
    const float* x   = (const float*)d_in[0];
    const void*  ei  = d_in[1];
    const float* W1  = (const float*)d_in[2];
    const float* b1  = (const float*)d_in[3];
    const float* W2  = (const float*)d_in[4];
    const float* b2  = (const float*)d_in[5];
    const float* Wl  = (const float*)d_in[6];
    const float* bl  = (const float*)d_in[7];
    float* out       = (float*)d_out;

    const int N = in_sizes[0] / 32;
    const int E = in_sizes[1] / 2;
    const int T = 256;

    int nodd = 2 * E < 512 ? 2 * E : 512;  // odd-word scan range for detect

    k_fill<<<(E + T - 1) / T, T>>>(ei, E, nodd);

    const int GW32 = (N * 32 + T - 1) / T;  // warp-per-node
    const int GW16 = (N * 16 + T - 1) / T;  // 16 lanes/node

    k_dinv_xs<<<GW32, T>>>(x, N);
    k_gather_x<<<GW16, T>>>(N);
    k_gemm_fused<<<(N + 127) / 128, 128>>>(W1, b1, W2, N);
    k_gather_head<<<GW16, T>>>(b2, Wl, bl, out, N);
}